// round 6
// baseline (speedup 1.0000x reference)
#include <cuda_runtime.h>
#include <math.h>

// Problem constants (fixed shapes per reference)
#define SEGS 65536
#define NPTS 16777216

// ---------------- scratch (device globals; no allocation allowed) ----------
__device__ int    g_cnt[SEGS];        // histogram counts
__device__ int    g_base[SEGS];       // exclusive prefix offsets (stable)
__device__ int    g_cursor[SEGS];     // working write cursors
__device__ float4 g_sorted[NPTS];     // segment-sorted points {x,y,z,unused}
__device__ float4 g_stats[SEGS];      // {mean.x, mean.y, mean.z, 1/(diam+0.01)}

// ---------------- pass 0: reset histogram ----------------------------------
__global__ void k_init() {
    int t = blockIdx.x * blockDim.x + threadIdx.x;
    if (t < SEGS) g_cnt[t] = 0;
}

// ---------------- pass 1: histogram of segment ids -------------------------
__global__ __launch_bounds__(256, 8)
void k_hist(const int4* __restrict__ idx4, int nq) {
    int stride = gridDim.x * blockDim.x;
    for (int q = blockIdx.x * blockDim.x + threadIdx.x; q < nq; q += stride) {
        int4 s = idx4[q];
        atomicAdd(&g_cnt[s.x], 1);
        atomicAdd(&g_cnt[s.y], 1);
        atomicAdd(&g_cnt[s.z], 1);
        atomicAdd(&g_cnt[s.w], 1);
    }
}

// ---------------- pass 2: exclusive prefix sum (one block) -----------------
// 1024 threads, each owns 64 consecutive segments.
__global__ __launch_bounds__(1024, 1)
void k_scan() {
    __shared__ int sums[1024];
    int t = threadIdx.x;
    int base = t * 64;
    int acc = 0;
    #pragma unroll 4
    for (int i = 0; i < 64; i++) acc += g_cnt[base + i];
    sums[t] = acc;
    __syncthreads();
    // Hillis-Steele inclusive scan over 1024 partials
    for (int off = 1; off < 1024; off <<= 1) {
        int v = (t >= off) ? sums[t - off] : 0;
        __syncthreads();
        sums[t] += v;
        __syncthreads();
    }
    int run = sums[t] - acc;   // exclusive prefix of this thread's chunk
    #pragma unroll 4
    for (int i = 0; i < 64; i++) {
        int c = g_cnt[base + i];
        g_base[base + i]   = run;
        g_cursor[base + i] = run;
        run += c;
    }
}

// ---------------- pass 3: scatter points into segment-sorted order ---------
// g_sorted is write-once streaming (268MB > L2): use evict-first stores.
__global__ __launch_bounds__(256, 8)
void k_scatterpts(const float4* __restrict__ pos4,
                  const int4* __restrict__ idx4, int nq) {
    int stride = gridDim.x * blockDim.x;
    for (int q = blockIdx.x * blockDim.x + threadIdx.x; q < nq; q += stride) {
        float4 a = pos4[3 * q + 0];   // p0.xyz p1.x
        float4 b = pos4[3 * q + 1];   // p1.yz  p2.xy
        float4 c = pos4[3 * q + 2];   // p2.z   p3.xyz
        int4 s = idx4[q];
        int p0 = atomicAdd(&g_cursor[s.x], 1);
        int p1 = atomicAdd(&g_cursor[s.y], 1);
        int p2 = atomicAdd(&g_cursor[s.z], 1);
        int p3 = atomicAdd(&g_cursor[s.w], 1);
        __stcs(&g_sorted[p0], make_float4(a.x, a.y, a.z, 0.f));
        __stcs(&g_sorted[p1], make_float4(a.w, b.x, b.y, 0.f));
        __stcs(&g_sorted[p2], make_float4(b.z, b.w, c.x, 0.f));
        __stcs(&g_sorted[p3], make_float4(c.y, c.z, c.w, 0.f));
    }
}

// ---------------- pass 4: per-segment reduce + finalize (no atomics) -------
// One warp per segment; points are contiguous in g_sorted (read-once: __ldcs).
__global__ __launch_bounds__(256, 8)
void k_segreduce(float* __restrict__ diam_out) {
    int warp = (blockIdx.x * blockDim.x + threadIdx.x) >> 5;
    int lane = threadIdx.x & 31;
    if (warp >= SEGS) return;
    int start = g_base[warp];
    int cnt   = g_cnt[warp];

    float mnx =  INFINITY, mny =  INFINITY, mnz =  INFINITY;
    float mxx = -INFINITY, mxy = -INFINITY, mxz = -INFINITY;
    float sx = 0.f, sy = 0.f, sz = 0.f;
    for (int i = lane; i < cnt; i += 32) {
        float4 p = __ldcs(&g_sorted[start + i]);
        mnx = fminf(mnx, p.x); mny = fminf(mny, p.y); mnz = fminf(mnz, p.z);
        mxx = fmaxf(mxx, p.x); mxy = fmaxf(mxy, p.y); mxz = fmaxf(mxz, p.z);
        sx += p.x; sy += p.y; sz += p.z;
    }
    #pragma unroll
    for (int off = 16; off > 0; off >>= 1) {
        mnx = fminf(mnx, __shfl_xor_sync(0xFFFFFFFFu, mnx, off));
        mny = fminf(mny, __shfl_xor_sync(0xFFFFFFFFu, mny, off));
        mnz = fminf(mnz, __shfl_xor_sync(0xFFFFFFFFu, mnz, off));
        mxx = fmaxf(mxx, __shfl_xor_sync(0xFFFFFFFFu, mxx, off));
        mxy = fmaxf(mxy, __shfl_xor_sync(0xFFFFFFFFu, mxy, off));
        mxz = fmaxf(mxz, __shfl_xor_sync(0xFFFFFFFFu, mxz, off));
        sx += __shfl_xor_sync(0xFFFFFFFFu, sx, off);
        sy += __shfl_xor_sync(0xFFFFFFFFu, sy, off);
        sz += __shfl_xor_sync(0xFFFFFFFFu, sz, off);
    }
    if (lane == 0) {
        float diam, mx_, my_, mz_;
        if (cnt > 0) {
            float inv_c = 1.0f / (float)cnt;
            mx_ = sx * inv_c; my_ = sy * inv_c; mz_ = sz * inv_c;
            diam = fmaxf(mxx - mnx, fmaxf(mxy - mny, mxz - mnz));
        } else {
            // jax identities: min=+inf, max=-inf -> diam=-inf; sum=0 -> mean=0
            mx_ = my_ = mz_ = 0.0f;
            diam = -INFINITY;
        }
        diam_out[warp] = diam;
        float4 st;
        st.x = mx_; st.y = my_; st.z = mz_;
        st.w = 1.0f / (diam + 0.01f);
        g_stats[warp] = st;
    }
}

// ---------------- pass 5: gather + normalize (measured 121.6us) ------------
__global__ __launch_bounds__(256, 8)
void k_normalize4(const float4* __restrict__ pos4,
                  const int4* __restrict__ idx4,
                  float4* __restrict__ out4, int nq) {
    int stride = gridDim.x * blockDim.x;
    for (int q = blockIdx.x * blockDim.x + threadIdx.x; q < nq; q += stride) {
        float4 a = pos4[3 * q + 0];
        float4 b = pos4[3 * q + 1];
        float4 c = pos4[3 * q + 2];
        int4 s = idx4[q];
        float4 s0 = __ldg(&g_stats[s.x]);   // 1MB table, L2-resident
        float4 s1 = __ldg(&g_stats[s.y]);
        float4 s2 = __ldg(&g_stats[s.z]);
        float4 s3 = __ldg(&g_stats[s.w]);
        float4 o0, o1, o2;
        o0.x = (a.x - s0.x) * s0.w;
        o0.y = (a.y - s0.y) * s0.w;
        o0.z = (a.z - s0.z) * s0.w;
        o0.w = (a.w - s1.x) * s1.w;
        o1.x = (b.x - s1.y) * s1.w;
        o1.y = (b.y - s1.z) * s1.w;
        o1.z = (b.z - s2.x) * s2.w;
        o1.w = (b.w - s2.y) * s2.w;
        o2.x = (c.x - s2.z) * s2.w;
        o2.y = (c.y - s3.x) * s3.w;
        o2.z = (c.z - s3.y) * s3.w;
        o2.w = (c.w - s3.z) * s3.w;
        out4[3 * q + 0] = o0;
        out4[3 * q + 1] = o1;
        out4[3 * q + 2] = o2;
    }
}

// ---------------- launch ----------------------------------------------------
extern "C" void kernel_launch(void* const* d_in, const int* in_sizes, int n_in,
                              void* d_out, int out_size) {
    const float* pos = (const float*)d_in[0];
    const int*   idx = (const int*)d_in[1];
    int n = in_sizes[1];               // point count from idx length (16777216)

    float* out  = (float*)d_out;       // [N*3] normalized points
    float* diam = out + (size_t)n * 3; // [S] diameters follow

    const int T = 256;
    int nq = n / 4;                    // N is a multiple of 4
    int grid_pts = (nq + T - 1) / T;
    if (grid_pts > 148 * 32) grid_pts = 148 * 32;

    k_init<<<(SEGS + T - 1) / T, T>>>();
    k_hist<<<grid_pts, T>>>((const int4*)idx, nq);
    k_scan<<<1, 1024>>>();
    k_scatterpts<<<grid_pts, T>>>((const float4*)pos, (const int4*)idx, nq);
    k_segreduce<<<(SEGS * 32 + T - 1) / T, T>>>(diam);
    k_normalize4<<<grid_pts, T>>>((const float4*)pos, (const int4*)idx,
                                  (float4*)out, nq);
}